// round 2
// baseline (speedup 1.0000x reference)
#include <cuda_runtime.h>
#include <cuda_bf16.h>
#include <math.h>

// Problem constants
#define SQ   1024   // sequence length
#define DM   1024   // model dim
#define NH   16     // heads
#define DKH  64     // per-head dim
#define BSZ  2      // batch
#define MROWS (BSZ*SQ)   // 2048 rows for GEMMs

// Scratch (static device globals -- allocation-free per harness rules)
__device__ float g_W[4][DM*DM];        // big quaternion weight matrices q,k,v,o (16 MB)
__device__ float g_P[3][MROWS*DM];     // projected Q,K,V in [B*S, D] layout (24 MB)
__device__ float g_O[MROWS*DM];        // attention output, concat-head layout (8 MB)

// Quaternion block tables: SRC[rb*4+cb] = source component, SGN = sign.
// (Same involution serves both Wbig construction and the output combine.)
__constant__ int   c_SRC[16] = {0,1,2,3,  1,0,3,2,  2,3,0,1,  3,2,1,0};
__constant__ float c_SGN[16] = {1.f,1.f,1.f,1.f,  -1.f,1.f,-1.f,1.f,
                                -1.f,1.f,1.f,-1.f, -1.f,-1.f,1.f,1.f};

struct WPtrs { const float* w[16]; };

// ---------------------------------------------------------------------------
// Build the 4 big 1024x1024 weight matrices from the 16 (256x256) components.
// Wbig[rb*256+kk][cb*256+nn] = SGN[rb][cb] * w_{SRC[rb][cb]}[kk][nn]
// ---------------------------------------------------------------------------
__global__ void build_wbig_kernel(WPtrs p) {
    int idx   = blockIdx.x * 256 + threadIdx.x;   // 4 * 1M total
    int which = idx >> 20;
    int e     = idx & ((1 << 20) - 1);
    int k     = e >> 10;
    int n     = e & 1023;
    int rb = k >> 8, kk = k & 255;
    int cb = n >> 8, nn = n & 255;
    float v = c_SGN[rb*4+cb] * p.w[which*4 + c_SRC[rb*4+cb]][kk*256 + nn];
    g_W[which][k*DM + n] = v;
}

// ---------------------------------------------------------------------------
// SGEMM with bias: C[M,1024] = A[M,1024] @ W[1024,1024] + bias
// 128x128 tile, BK=16, 256 threads, 8x8 per thread.
// asel: 0 -> use Ain param, 1 -> g_O.  csel: 0..2 -> g_P[csel], 3 -> Cout.
// ---------------------------------------------------------------------------
__global__ __launch_bounds__(256)
void sgemm_bias_kernel(const float* __restrict__ Ain, int asel, int wsel,
                       const float* __restrict__ bias,
                       float* __restrict__ Cout, int csel)
{
    const float* A = (asel == 0) ? Ain : g_O;
    const float* W = g_W[wsel];
    float* C = (csel < 3) ? g_P[csel] : Cout;

    __shared__ float As[16][128];   // A transposed: [k][m]
    __shared__ float Bs[16][128];   // [k][n]

    int tid = threadIdx.x;
    int m0 = blockIdx.y * 128, n0 = blockIdx.x * 128;
    int tm = (tid >> 4) * 8, tn = (tid & 15) * 8;

    float acc[8][8];
#pragma unroll
    for (int i = 0; i < 8; i++)
#pragma unroll
        for (int j = 0; j < 8; j++) acc[i][j] = 0.f;

    for (int k0 = 0; k0 < DM; k0 += 16) {
#pragma unroll
        for (int i = 0; i < 2; i++) {
            int idx = tid + i * 256;                 // 0..511
            int ar = idx >> 2, akc = (idx & 3) * 4;  // A: 128 rows x 4 float4
            float4 a = *(const float4*)(A + (size_t)(m0 + ar) * DM + k0 + akc);
            As[akc + 0][ar] = a.x; As[akc + 1][ar] = a.y;
            As[akc + 2][ar] = a.z; As[akc + 3][ar] = a.w;
            int br = idx >> 5, bc = (idx & 31) * 4;  // B: 16 rows x 32 float4
            *(float4*)&Bs[br][bc] =
                *(const float4*)(W + (size_t)(k0 + br) * DM + n0 + bc);
        }
        __syncthreads();
#pragma unroll
        for (int k = 0; k < 16; k++) {
            float a[8], b[8];
            *(float4*)(a)     = *(float4*)&As[k][tm];
            *(float4*)(a + 4) = *(float4*)&As[k][tm + 4];
            *(float4*)(b)     = *(float4*)&Bs[k][tn];
            *(float4*)(b + 4) = *(float4*)&Bs[k][tn + 4];
#pragma unroll
            for (int i = 0; i < 8; i++)
#pragma unroll
                for (int j = 0; j < 8; j++) acc[i][j] += a[i] * b[j];
        }
        __syncthreads();
    }

#pragma unroll
    for (int i = 0; i < 8; i++) {
        float out[8];
#pragma unroll
        for (int j = 0; j < 8; j++) out[j] = acc[i][j] + bias[n0 + tn + j];
        float* crow = C + (size_t)(m0 + tm + i) * DM + n0 + tn;
        *(float4*)(crow)     = *(float4*)(out);
        *(float4*)(crow + 4) = *(float4*)(out + 4);
    }
}

// ---------------------------------------------------------------------------
// Quaternion flash attention.
// Grid: (S/32, B*H). Block: 256 threads = (tx 0..15 over 64 key cols /4,
// ty 0..15 over 32 query rows /2). 4 softmax channels, each with its own
// online max/denominator and unnormalized accumulator U_c[m][0:64].
// ---------------------------------------------------------------------------
#define ATT_SMEM_FLOATS (2048 + 4160 + 4096 + 8192)

__global__ __launch_bounds__(256)
void quat_attn_kernel(const int* __restrict__ mask)
{
    extern __shared__ float smemf[];
    float* Qs = smemf;                    // [32][64]
    float* Ks = smemf + 2048;             // [64][65] padded
    float* Vs = smemf + 2048 + 4160;      // [64][64]
    float* Ps = smemf + 2048 + 4160 + 4096; // [4][32][64]; reused for A at end

    int tid = threadIdx.x;
    int tx = tid & 15, ty = tid >> 4;
    int bh = blockIdx.y;
    int b = bh >> 4, h = bh & 15;
    int q0 = blockIdx.x * 32;

    const float* Qg = g_P[0] + (size_t)(b * SQ) * DM + h * DKH;
    const float* Kg = g_P[1] + (size_t)(b * SQ) * DM + h * DKH;
    const float* Vg = g_P[2] + (size_t)(b * SQ) * DM + h * DKH;
    const int*   mrow = mask + b * SQ;

    // Load Q tile (32 x 64)
#pragma unroll
    for (int i = 0; i < 2; i++) {
        int idx = tid + i * 256;
        int r = idx >> 4, cc = (idx & 15) * 4;
        *(float4*)&Qs[r * 64 + cc] =
            *(const float4*)(Qg + (size_t)(q0 + r) * DM + cc);
    }

    float mrun[4][2], lrun[4][2], U[4][2][4];
#pragma unroll
    for (int ch = 0; ch < 4; ch++)
#pragma unroll
        for (int im = 0; im < 2; im++) {
            mrun[ch][im] = -1e30f;
            lrun[ch][im] = 0.f;
#pragma unroll
            for (int j = 0; j < 4; j++) U[ch][im][j] = 0.f;
        }

    for (int n0 = 0; n0 < SQ; n0 += 64) {
        __syncthreads();   // previous PV done before overwriting K/V
        // Load K (padded rows) and V tiles (64 x 64)
#pragma unroll
        for (int i = 0; i < 4; i++) {
            int idx = tid + i * 256;
            int r = idx >> 4, cc = (idx & 15) * 4;
            float4 k4 = *(const float4*)(Kg + (size_t)(n0 + r) * DM + cc);
            Ks[r * 65 + cc + 0] = k4.x; Ks[r * 65 + cc + 1] = k4.y;
            Ks[r * 65 + cc + 2] = k4.z; Ks[r * 65 + cc + 3] = k4.w;
            *(float4*)&Vs[r * 64 + cc] =
                *(const float4*)(Vg + (size_t)(n0 + r) * DM + cc);
        }
        __syncthreads();

        // ---- Scores: 4 channels jointly, contraction over t=0..15 quads ----
        float sc[4][2][4];
#pragma unroll
        for (int ch = 0; ch < 4; ch++)
#pragma unroll
            for (int im = 0; im < 2; im++)
#pragma unroll
                for (int in = 0; in < 4; in++) sc[ch][im][in] = 0.f;

#pragma unroll 4
        for (int t = 0; t < 16; t++) {
            float qv[2][4], kv[4][4];
#pragma unroll
            for (int im = 0; im < 2; im++)
#pragma unroll
                for (int ch = 0; ch < 4; ch++)
                    qv[im][ch] = Qs[(ty * 2 + im) * 64 + ch * 16 + t];
#pragma unroll
            for (int in = 0; in < 4; in++)
#pragma unroll
                for (int ch = 0; ch < 4; ch++)
                    kv[in][ch] = Ks[(tx * 4 + in) * 65 + ch * 16 + t];
#pragma unroll
            for (int im = 0; im < 2; im++) {
                float ar = qv[im][0], ax = qv[im][1], ay = qv[im][2], az = qv[im][3];
#pragma unroll
                for (int in = 0; in < 4; in++) {
                    float br = kv[in][0], bx = kv[in][1], by = kv[in][2], bz = kv[in][3];
                    sc[0][im][in] += ar * br - ax * bx - ay * by - az * bz;
                    sc[1][im][in] += ar * bx + ax * br + ay * bz - az * by;
                    sc[2][im][in] += ar * by - ax * bz + ay * br + az * bx;
                    sc[3][im][in] += ar * bz + ax * by - ay * bx + az * br;
                }
            }
        }

        // ---- Mask + per-channel online softmax ----
        int mk[4];
#pragma unroll
        for (int in = 0; in < 4; in++) mk[in] = mrow[n0 + tx * 4 + in];

#pragma unroll
        for (int ch = 0; ch < 4; ch++) {
#pragma unroll
            for (int im = 0; im < 2; im++) {
                float s[4];
#pragma unroll
                for (int in = 0; in < 4; in++) {
                    float v = sc[ch][im][in] * 0.125f;   // 1/sqrt(64)
                    s[in] = mk[in] ? v : -1e9f;
                }
                float tmax = fmaxf(fmaxf(s[0], s[1]), fmaxf(s[2], s[3]));
#pragma unroll
                for (int off = 8; off > 0; off >>= 1)
                    tmax = fmaxf(tmax, __shfl_xor_sync(0xffffffffu, tmax, off));
                float mnew = fmaxf(mrun[ch][im], tmax);
                float corr = __expf(mrun[ch][im] - mnew);
                float p[4], ps = 0.f;
#pragma unroll
                for (int in = 0; in < 4; in++) { p[in] = __expf(s[in] - mnew); ps += p[in]; }
#pragma unroll
                for (int off = 8; off > 0; off >>= 1)
                    ps += __shfl_xor_sync(0xffffffffu, ps, off);
                lrun[ch][im] = lrun[ch][im] * corr + ps;
                mrun[ch][im] = mnew;
#pragma unroll
                for (int j = 0; j < 4; j++) U[ch][im][j] *= corr;
                *(float4*)&Ps[ch * 2048 + (ty * 2 + im) * 64 + tx * 4] =
                    make_float4(p[0], p[1], p[2], p[3]);
            }
        }
        __syncthreads();

        // ---- P @ V accumulation: U_c[m][d] += P_c[m][n] * V[n][d] ----
#pragma unroll 8
        for (int n = 0; n < 64; n++) {
            float4 v = *(float4*)&Vs[n * 64 + tx * 4];
#pragma unroll
            for (int ch = 0; ch < 4; ch++)
#pragma unroll
                for (int im = 0; im < 2; im++) {
                    float p = Ps[ch * 2048 + (ty * 2 + im) * 64 + n];
                    U[ch][im][0] += p * v.x;
                    U[ch][im][1] += p * v.y;
                    U[ch][im][2] += p * v.z;
                    U[ch][im][3] += p * v.w;
                }
        }
    }

    __syncthreads();
    // Normalize A_c = U_c / l_c into Ps region
#pragma unroll
    for (int ch = 0; ch < 4; ch++)
#pragma unroll
        for (int im = 0; im < 2; im++) {
            float inv = 1.f / lrun[ch][im];
            *(float4*)&Ps[ch * 2048 + (ty * 2 + im) * 64 + tx * 4] =
                make_float4(U[ch][im][0] * inv, U[ch][im][1] * inv,
                            U[ch][im][2] * inv, U[ch][im][3] * inv);
        }
    __syncthreads();

    // Quaternion combine + write:  O_oc[:,u] = sum_c SGN[c][oc]*A_c[:, SRC[c][oc]*16+u]
    float* Og = g_O + (size_t)(b * SQ) * DM + h * DKH;
#pragma unroll
    for (int im = 0; im < 2; im++) {
        int m = ty * 2 + im;
#pragma unroll
        for (int j = 0; j < 4; j++) {
            int col = tx * 4 + j;
            int oc = col >> 4, u = col & 15;
            float o = 0.f;
#pragma unroll
            for (int ch = 0; ch < 4; ch++)
                o += c_SGN[ch * 4 + oc] *
                     Ps[ch * 2048 + m * 64 + c_SRC[ch * 4 + oc] * 16 + u];
            Og[(size_t)(q0 + m) * DM + col] = o;
        }
    }
}

// ---------------------------------------------------------------------------
extern "C" void kernel_launch(void* const* d_in, const int* in_sizes, int n_in,
                              void* d_out, int out_size)
{
    (void)in_sizes; (void)n_in; (void)out_size;
    // metadata.txt order = setup_inputs() dict insertion order:
    //  0 q, 1 k, 2 v, 3 mask,
    //  4-7  wq_r, wq_i, wq_j, wq_k,
    //  8-11 wk_r, wk_i, wk_j, wk_k,
    // 12-15 wv_r, wv_i, wv_j, wv_k,
    // 16-19 wo_r, wo_i, wo_j, wo_k,
    // 20 bq, 21 bk, 22 bv, 23 bo
    WPtrs wp;
    for (int i = 0; i < 16; i++) wp.w[i] = (const float*)d_in[4 + i];

    build_wbig_kernel<<<(4 * DM * DM) / 256, 256>>>(wp);

    dim3 ggrid(DM / 128, MROWS / 128);   // (8, 16)
    sgemm_bias_kernel<<<ggrid, 256>>>((const float*)d_in[0], 0, 0,
                                      (const float*)d_in[20], nullptr, 0);
    sgemm_bias_kernel<<<ggrid, 256>>>((const float*)d_in[1], 0, 1,
                                      (const float*)d_in[21], nullptr, 1);
    sgemm_bias_kernel<<<ggrid, 256>>>((const float*)d_in[2], 0, 2,
                                      (const float*)d_in[22], nullptr, 2);

    int smem = ATT_SMEM_FLOATS * 4;      // 73984 B
    cudaFuncSetAttribute(quat_attn_kernel,
                         cudaFuncAttributeMaxDynamicSharedMemorySize, smem);
    quat_attn_kernel<<<dim3(SQ / 32, BSZ * NH), 256, smem>>>((const int*)d_in[3]);

    sgemm_bias_kernel<<<ggrid, 256>>>(nullptr, 1, 3,
                                      (const float*)d_in[23], (float*)d_out, 3);
}